// round 16
// baseline (speedup 1.0000x reference)
#include <cuda_runtime.h>
#include <cuda_fp16.h>
#include <cstdint>

#define NROWS 131072
#define DIN   512
#define NH    512
#define DOUT  128
#define NBOUNDS 24

// ---------------- device scratch ---------------------------------------------
__device__ __align__(256) __half g_act0[(size_t)NROWS * 512];  // discretize out
// weights transposed [N][K], single fp16 plane
__device__ __align__(256) __half g_wi[NH * DIN];
__device__ __align__(256) __half g_wh[NH * NH];
__device__ __align__(256) __half g_wo[DOUT * NH];
__device__ unsigned g_min_enc[DIN];
__device__ unsigned g_max_enc[DIN];

// ---------------- helpers ----------------------------------------------------
__device__ __forceinline__ uint32_t smem_u32(const void* p) {
    uint32_t a;
    asm("{ .reg .u64 t; cvta.to.shared.u64 t, %1; cvt.u32.u64 %0, t; }"
        : "=r"(a) : "l"(p));
    return a;
}
__device__ __forceinline__ void ldsm4(uint32_t* r, uint32_t a) {
    asm volatile("ldmatrix.sync.aligned.m8n8.x4.shared.b16 {%0,%1,%2,%3}, [%4];"
                 : "=r"(r[0]), "=r"(r[1]), "=r"(r[2]), "=r"(r[3]) : "r"(a));
}
__device__ __forceinline__ void mma16816h(float* d, const uint32_t* a,
                                          uint32_t b0, uint32_t b1) {
    asm volatile(
        "mma.sync.aligned.m16n8k16.row.col.f32.f16.f16.f32 "
        "{%0,%1,%2,%3}, {%4,%5,%6,%7}, {%8,%9}, {%0,%1,%2,%3};"
        : "+f"(d[0]), "+f"(d[1]), "+f"(d[2]), "+f"(d[3])
        : "r"(a[0]), "r"(a[1]), "r"(a[2]), "r"(a[3]), "r"(b0), "r"(b1));
}
#define CP_ASYNC16(dst, src) \
    asm volatile("cp.async.cg.shared.global [%0], [%1], 16;" :: "r"(dst), "l"(src))
#define CP_COMMIT() asm volatile("cp.async.commit_group;" ::: "memory")
#define CP_WAIT0()  asm volatile("cp.async.wait_group 0;" ::: "memory")

// ---------------- min/max + discretize ---------------------------------------
__device__ __forceinline__ unsigned enc_f(float f) {
    unsigned u = __float_as_uint(f);
    return (u & 0x80000000u) ? ~u : (u | 0x80000000u);
}
__device__ __forceinline__ float dec_f(unsigned e) {
    unsigned u = (e & 0x80000000u) ? (e & 0x7FFFFFFFu) : ~e;
    return __uint_as_float(u);
}
__global__ void init_minmax() {
    int i = threadIdx.x;
    g_min_enc[i] = 0xFFFFFFFFu;
    g_max_enc[i] = 0x00000000u;
}
__global__ void colminmax(const float* __restrict__ x) {
    const int col = threadIdx.x;
    const size_t base = (size_t)blockIdx.x * 512 * DIN + col;
    float v0 = x[base];
    float mn = v0, mx = v0;
    for (int r = 1; r < 512; r++) {
        float v = x[base + (size_t)r * DIN];
        mn = fminf(mn, v);
        mx = fmaxf(mx, v);
    }
    atomicMin(&g_min_enc[col], enc_f(mn));
    atomicMax(&g_max_enc[col], enc_f(mx));
}
// Windowed bucketize: candidate bin from scaled position, then 6 exact
// boundary compares (covers the <=1.5-bin error of the exact formula).
__global__ void discretize(const float* __restrict__ x) {
    __shared__ float sh_frac[NBOUNDS];
    const int col = threadIdx.x;
    if (col < NBOUNDS) sh_frac[col] = __fdiv_rn((float)(col + 1), 25.0f);
    __syncthreads();
    const float bmin = dec_f(g_min_enc[col]);
    const float bmax = dec_f(g_max_enc[col]);
    const float range = __fsub_rn(bmax, bmin);
    const float s = range > 0.0f ? __fdiv_rn(25.0f, range) : 0.0f;
    const size_t base = (size_t)blockIdx.x * 512 * DIN + col;
    for (int r = 0; r < 512; r++) {
        float v = x[base + (size_t)r * DIN];
        float t = (v - bmin) * s;
        int c = (int)t;
        int b0 = min(max(c - 3, 0), 18);
        int idx = b0;
#pragma unroll
        for (int j = 0; j < 6; j++) {
            float bk = __fadd_rn(bmin, __fmul_rn(range, sh_frac[b0 + j]));
            idx += (bk < v) ? 1 : 0;
        }
        g_act0[base + (size_t)r * DIN] = __float2half_rn((float)idx);
    }
}

// ---------------- weight convert + transpose (single fp16 plane) -------------
__global__ void wprep(const float* __restrict__ W, __half* __restrict__ hi,
                      int N, int K) {
    int i = blockIdx.x * blockDim.x + threadIdx.x;
    if (i >= N * K) return;
    int k = i / N, n = i % N;  // W is [K][N]
    hi[(size_t)n * K + k] = __float2half_rn(W[i]);  // transposed [N][K]
}

// ---------------- fused 7-layer MLP ------------------------------------------
// One CTA owns 64 M-rows through all layers; activations stay in SMEM.
// 512 threads = 16 warps (2m x 8n), warp tile 32x64 over out 64x512.
// SMEM: ACT 64KB (8 chunk-blocks of 64 rows x 128B, swizzled) +
//       2 x 64KB W double buffer (512 rows x 128B per BK=64 chunk).
#define SM_ACT 0
#define SM_W0  65536
#define SM_W1  131072
#define SM_TOT 196608

__global__ __launch_bounds__(512, 1)
void mlp_fused(const __half* __restrict__ act0,
               const __half* __restrict__ Wi, const __half* __restrict__ Wh,
               const __half* __restrict__ Wo,
               const float* __restrict__ b_in, const float* __restrict__ b_h,
               const float* __restrict__ b_out, float* __restrict__ out) {
    extern __shared__ __align__(1024) unsigned char sm[];
    const uint32_t smb = smem_u32(sm);
    const uint32_t ACT = smb + SM_ACT;
    const int tid = threadIdx.x;
    const int lane = tid & 31, wid = tid >> 5;
    const int wm = wid >> 3, wn = wid & 7;      // 2m x 8n warp grid
    const int m0 = blockIdx.x * 64;

    // ---- prologue: act0 tile -> swizzled chunk blocks ----------------------
#pragma unroll
    for (int it = 0; it < 8; it++) {
        int idx = tid + it * 512;               // 0..4095 slots of 16B
        int s = idx & 7;
        int r = (idx >> 3) & 63;
        int chk = idx >> 9;                     // 0..7
        uint32_t dst = ACT + chk * 8192 + r * 128 + ((uint32_t)(s ^ (r & 7)) << 4);
        CP_ASYNC16(dst, act0 + (size_t)(m0 + r) * 512 + chk * 64 + s * 8);
    }
    CP_COMMIT(); CP_WAIT0();
    __syncthreads();

    const int arow = lane & 15, kbl = lane >> 4;
    uint32_t aoff[2]; int amod[2];
#pragma unroll
    for (int mf = 0; mf < 2; mf++) {
        int r = wm * 32 + mf * 16 + arow;       // 0..63
        aoff[mf] = r * 128; amod[mf] = r & 7;
    }
    uint32_t boff[4]; int bmod[4];
#pragma unroll
    for (int g = 0; g < 4; g++) {
        int r = wn * 64 + g * 16 + arow;        // 0..511
        boff[g] = r * 128; bmod[g] = r & 7;
    }
    const int qr = lane >> 2, qc = lane & 3;

#pragma unroll 1
    for (int L = 0; L < 7; L++) {
        const __half* W   = (L == 0) ? Wi  : (L < 6) ? Wh  : Wo;
        const float* bias = (L == 0) ? b_in : (L < 6) ? b_h : b_out;
        const bool fin = (L == 6);
        const int witers = fin ? 2 : 8;         // (nrows*8)/512 cp per thread
        const bool active = !fin || (wn < 2);   // final: only N=128 covered

        float acc[2][8][4];
#pragma unroll
        for (int i = 0; i < 2; i++)
#pragma unroll
            for (int j = 0; j < 8; j++)
#pragma unroll
                for (int q = 0; q < 4; q++) acc[i][j][q] = 0.f;

        auto wload = [&](int ch) {
            uint32_t wb = smb + ((ch & 1) ? SM_W1 : SM_W0);
            for (int it = 0; it < witers; it++) {
                int idx = tid + it * 512;
                int s = idx & 7;
                int r = idx >> 3;               // W row (N index)
                uint32_t dst = wb + r * 128 + ((uint32_t)(s ^ (r & 7)) << 4);
                CP_ASYNC16(dst, W + (size_t)r * 512 + ch * 64 + s * 8);
            }
        };

        wload(0); CP_COMMIT();
#pragma unroll 1
        for (int ch = 0; ch < 8; ch++) {
            CP_WAIT0();
            __syncthreads();                    // chunk ready + prev buffer free
            if (ch < 7) { wload(ch + 1); CP_COMMIT(); }

            const uint32_t wb = smb + ((ch & 1) ? SM_W1 : SM_W0);
            const uint32_t ab = ACT + ch * 8192;
#pragma unroll
            for (int kk = 0; kk < 4; kk++) {
                const int c = kk * 2 + kbl;
                uint32_t af[2][4], bf[4][4];
#pragma unroll
                for (int mf = 0; mf < 2; mf++)
                    ldsm4(af[mf], ab + aoff[mf] + (uint32_t)((c ^ amod[mf]) << 4));
                if (active) {
#pragma unroll
                    for (int g = 0; g < 4; g++)
                        ldsm4(bf[g], wb + boff[g] + (uint32_t)((c ^ bmod[g]) << 4));
#pragma unroll
                    for (int g = 0; g < 4; g++)
#pragma unroll
                        for (int mf = 0; mf < 2; mf++) {
                            mma16816h(acc[mf][2 * g],     af[mf], bf[g][0], bf[g][2]);
                            mma16816h(acc[mf][2 * g + 1], af[mf], bf[g][1], bf[g][3]);
                        }
                }
            }
        }
        __syncthreads();                        // all A reads done before overwrite

        if (fin) {
            if (active) {
#pragma unroll
                for (int mf = 0; mf < 2; mf++) {
                    const int r0 = m0 + wm * 32 + mf * 16 + qr;
#pragma unroll
                    for (int nf = 0; nf < 8; nf++) {
                        const int n = wn * 64 + nf * 8 + qc * 2;
                        const float bv0 = bias[n], bv1 = bias[n + 1];
                        const float* a = acc[mf][nf];
                        *reinterpret_cast<float2*>(out + (size_t)r0 * DOUT + n) =
                            make_float2(fmaxf(a[0] + bv0, 0.f), fmaxf(a[1] + bv1, 0.f));
                        *reinterpret_cast<float2*>(out + (size_t)(r0 + 8) * DOUT + n) =
                            make_float2(fmaxf(a[2] + bv0, 0.f), fmaxf(a[3] + bv1, 0.f));
                    }
                }
            }
        } else {
            // write act in place: col n -> chunk wn, slot nf, byte qc*4
#pragma unroll
            for (int mf = 0; mf < 2; mf++) {
                const int r0 = wm * 32 + mf * 16 + qr;
#pragma unroll
                for (int nf = 0; nf < 8; nf++) {
                    const int n = wn * 64 + nf * 8 + qc * 2;
                    const float bv0 = bias[n], bv1 = bias[n + 1];
                    const float* a = acc[mf][nf];
                    float v00 = fmaxf(a[0] + bv0, 0.f);
                    float v01 = fmaxf(a[1] + bv1, 0.f);
                    float v10 = fmaxf(a[2] + bv0, 0.f);
                    float v11 = fmaxf(a[3] + bv1, 0.f);
                    __half h00 = __float2half_rn(v00), h01 = __float2half_rn(v01);
                    __half h10 = __float2half_rn(v10), h11 = __float2half_rn(v11);
                    uint32_t p0 = (uint32_t)*reinterpret_cast<unsigned short*>(&h00) |
                                  ((uint32_t)*reinterpret_cast<unsigned short*>(&h01) << 16);
                    uint32_t p1 = (uint32_t)*reinterpret_cast<unsigned short*>(&h10) |
                                  ((uint32_t)*reinterpret_cast<unsigned short*>(&h11) << 16);
                    uint32_t base0 = ACT + wn * 8192 + (uint32_t)qc * 4 +
                                     ((uint32_t)(nf ^ (r0 & 7)) << 4) + r0 * 128;
                    uint32_t base1 = ACT + wn * 8192 + (uint32_t)qc * 4 +
                                     ((uint32_t)(nf ^ ((r0 + 8) & 7)) << 4) + (r0 + 8) * 128;
                    asm volatile("st.shared.b32 [%0], %1;" :: "r"(base0), "r"(p0) : "memory");
                    asm volatile("st.shared.b32 [%0], %1;" :: "r"(base1), "r"(p1) : "memory");
                }
            }
            __syncthreads();                    // act writes visible before next layer
        }
    }
}

// ---------------- tail zero --------------------------------------------------
__global__ void zero_tail(float* out, size_t start, size_t count) {
    size_t i = (size_t)blockIdx.x * blockDim.x + threadIdx.x;
    if (i < count) out[start + i] = 0.0f;
}

// ---------------- launch -----------------------------------------------------
extern "C" void kernel_launch(void* const* d_in, const int* in_sizes, int n_in,
                              void* d_out, int out_size) {
    const float* x     = (const float*)d_in[0];
    const float* W_in  = (const float*)d_in[1];
    const float* b_in  = (const float*)d_in[2];
    const float* W_h   = (const float*)d_in[3];
    const float* b_h   = (const float*)d_in[4];
    const float* W_out = (const float*)d_in[5];
    const float* b_out = (const float*)d_in[6];
    float* out = (float*)d_out;

    __half *act0, *wi, *wh, *wo;
    cudaGetSymbolAddress((void**)&act0, g_act0);
    cudaGetSymbolAddress((void**)&wi, g_wi);
    cudaGetSymbolAddress((void**)&wh, g_wh);
    cudaGetSymbolAddress((void**)&wo, g_wo);

    cudaFuncSetAttribute(mlp_fused, cudaFuncAttributeMaxDynamicSharedMemorySize,
                         SM_TOT);

    init_minmax<<<1, DIN>>>();
    wprep<<<(DIN * NH + 255) / 256, 256>>>(W_in, wi, NH, DIN);
    wprep<<<(NH * NH + 255) / 256, 256>>>(W_h, wh, NH, NH);
    wprep<<<(NH * DOUT + 255) / 256, 256>>>(W_out, wo, DOUT, NH);
    colminmax<<<NROWS / 512, DIN>>>(x);
    discretize<<<NROWS / 512, DIN>>>(x);     // -> g_act0 (exact ints in fp16)

    mlp_fused<<<NROWS / 64, 512, SM_TOT>>>(act0, wi, wh, wo,
                                           b_in, b_h, b_out, out);

    size_t y_elems = (size_t)NROWS * DOUT;
    if ((size_t)out_size > y_elems) {
        size_t cnt = (size_t)out_size - y_elems;
        zero_tail<<<(unsigned)((cnt + 255) / 256), 256>>>(out, y_elems, cnt);
    }
}